// round 1
// baseline (speedup 1.0000x reference)
#include <cuda_runtime.h>
#include <cstdint>

#define D        256
#define B        128
#define NC       10000
#define KP       (D / 2)      // 128 k-pairs (f32x2 packed along k)
#define NT       80           // n-tile per block
#define NBLK     (NC / NT)    // 125 blocks (one wave on 148 SMs)

// Scratch (device globals — no allocations allowed)
__device__ __align__(16) float g_leftT[KP * B * 2];   // [kp][b] as float2, flat floats
__device__ float g_lnorm[B];
__device__ __align__(16) float g_tT[KP * NC * 2];     // [kp][n] as float2, flat floats
__device__ float g_tnorm[NC];

// ---------------------------------------------------------------------------
// Kernel A: left[b][d] = ent[heads[b]][d] + rel[relations[b]][d]
// stored transposed as [kp][b] float2; also ||left_b||^2.
// ---------------------------------------------------------------------------
__global__ void build_left_kernel(const float* __restrict__ ent,
                                  const float* __restrict__ rel,
                                  const int* __restrict__ heads,
                                  const int* __restrict__ rels) {
    const int b = blockIdx.x;
    const int d = threadIdx.x;
    const int h = heads[b];
    const int r = rels[b];
    float v = ent[h * D + d] + rel[r * D + d];
    // float2 layout: flat float index = kp*(2B) + b*2 + (d&1)
    g_leftT[(d >> 1) * (2 * B) + b * 2 + (d & 1)] = v;

    float s = v * v;
    #pragma unroll
    for (int o = 16; o; o >>= 1) s += __shfl_xor_sync(0xffffffffu, s, o);
    __shared__ float ws[8];
    if ((threadIdx.x & 31) == 0) ws[threadIdx.x >> 5] = s;
    __syncthreads();
    if (threadIdx.x == 0) {
        float t = 0.f;
        #pragma unroll
        for (int i = 0; i < 8; i++) t += ws[i];
        g_lnorm[b] = t;
    }
}

// ---------------------------------------------------------------------------
// Kernel B: gather t = ent[tails[n]], store transposed [kp][n] float2 with
// coalesced writes (smem transpose), plus ||t_n||^2.
// Block: 256 threads handles 32 n-rows. Grid: ceil(NC/32) = 313.
// ---------------------------------------------------------------------------
#define TROWS 32
#define TPAD  129   // ull row stride (128 + 1) to dodge bank conflicts

__global__ void pack_t_kernel(const float* __restrict__ ent,
                              const int* __restrict__ tails) {
    __shared__ __align__(16) float tile[TROWS * TPAD * 2];  // [row][kp] as ull rows
    const int n0   = blockIdx.x * TROWS;
    const int warp = threadIdx.x >> 5;
    const int lane = threadIdx.x & 31;

    // load phase: 8 warps, each warp loads 4 rows (one n per warp per step)
    for (int rloc = warp; rloc < TROWS; rloc += 8) {
        int n = n0 + rloc;
        if (n < NC) {
            int row = tails[n];
            const float4* src = reinterpret_cast<const float4*>(ent + (size_t)row * D);
            float4 a = src[lane * 2];
            float4 c = src[lane * 2 + 1];
            float* tr = tile + rloc * (TPAD * 2) + lane * 8;
            tr[0] = a.x; tr[1] = a.y; tr[2] = a.z; tr[3] = a.w;
            tr[4] = c.x; tr[5] = c.y; tr[6] = c.z; tr[7] = c.w;
            float s = a.x*a.x + a.y*a.y + a.z*a.z + a.w*a.w
                    + c.x*c.x + c.y*c.y + c.z*c.z + c.w*c.w;
            #pragma unroll
            for (int o = 16; o; o >>= 1) s += __shfl_xor_sync(0xffffffffu, s, o);
            if (lane == 0) g_tnorm[n] = s;
        }
    }
    __syncthreads();

    // write phase: transposed, coalesced (consecutive lanes -> consecutive n)
    const unsigned long long* t2 = reinterpret_cast<const unsigned long long*>(tile);
    unsigned long long* dst = reinterpret_cast<unsigned long long*>(g_tT);
    for (int idx = threadIdx.x; idx < TROWS * KP; idx += 256) {
        int nl = idx & (TROWS - 1);
        int kp = idx >> 5;
        int n  = n0 + nl;
        if (n < NC) dst[(size_t)kp * NC + n] = t2[nl * TPAD + kp];
    }
}

// ---------------------------------------------------------------------------
// Kernel C: out[b][n] = -sqrt(||l||^2 + ||t||^2 - 2*dot(l,t))
// Block: 256 threads = 16(tx: n-groups) x 16(ty: b-groups).
// Per-thread micro-tile: 8 b x 5 n, packed f32x2 along k.
// smem: lefts [KP][B] float2 (128KB) + ts [KP][NT] float2 (80KB) = 208KB.
// ---------------------------------------------------------------------------
__device__ __forceinline__ unsigned long long fma2(unsigned long long a,
                                                   unsigned long long b,
                                                   unsigned long long c) {
    unsigned long long d;
    asm("fma.rn.f32x2 %0, %1, %2, %3;" : "=l"(d) : "l"(a), "l"(b), "l"(c));
    return d;
}

__global__ void __launch_bounds__(256, 1) score_kernel(float* __restrict__ out) {
    extern __shared__ __align__(16) float sm[];
    float* lefts = sm;                     // KP*B*2   = 32768 floats
    float* ts    = sm + KP * B * 2;        // KP*NT*2  = 20480 floats

    const int tid = threadIdx.x;
    const int nb  = blockIdx.x * NT;

    // fill smem (both sides coalesced: contiguous copies)
    #pragma unroll 8
    for (int i = tid; i < KP * B * 2; i += 256) lefts[i] = g_leftT[i];
    #pragma unroll 5
    for (int i = tid; i < KP * NT * 2; i += 256) {
        int kp = i / (NT * 2);
        int j  = i - kp * (NT * 2);
        ts[i] = g_tT[kp * (NC * 2) + nb * 2 + j];
    }
    __syncthreads();

    const int tx = tid & 15;   // n-group: n_local = tx*5 + j
    const int ty = tid >> 4;   // b-group: b = ty*8 + i

    const unsigned long long* Lp =
        reinterpret_cast<const unsigned long long*>(lefts) + ty * 8;
    const unsigned long long* Tp =
        reinterpret_cast<const unsigned long long*>(ts) + tx * 5;

    unsigned long long acc[8][5];
    #pragma unroll
    for (int i = 0; i < 8; i++)
        #pragma unroll
        for (int j = 0; j < 5; j++) acc[i][j] = 0ull;

    #pragma unroll 4
    for (int kp = 0; kp < KP; kp++) {
        unsigned long long lf[8], tf[5];
        const ulonglong2* lq = reinterpret_cast<const ulonglong2*>(Lp + kp * B);
        ulonglong2 q0 = lq[0], q1 = lq[1], q2 = lq[2], q3 = lq[3];
        lf[0] = q0.x; lf[1] = q0.y; lf[2] = q1.x; lf[3] = q1.y;
        lf[4] = q2.x; lf[5] = q2.y; lf[6] = q3.x; lf[7] = q3.y;
        const unsigned long long* tq = Tp + kp * NT;
        #pragma unroll
        for (int j = 0; j < 5; j++) tf[j] = tq[j];

        #pragma unroll
        for (int i = 0; i < 8; i++)
            #pragma unroll
            for (int j = 0; j < 5; j++)
                acc[i][j] = fma2(lf[i], tf[j], acc[i][j]);
    }

    float ln[8];
    #pragma unroll
    for (int i = 0; i < 8; i++) ln[i] = g_lnorm[ty * 8 + i];

    #pragma unroll
    for (int j = 0; j < 5; j++) {
        const int n = nb + tx * 5 + j;
        const float tn = g_tnorm[n];
        #pragma unroll
        for (int i = 0; i < 8; i++) {
            unsigned long long a = acc[i][j];
            float lo = __uint_as_float((unsigned)(a & 0xffffffffull));
            float hi = __uint_as_float((unsigned)(a >> 32));
            float v = ln[i] + tn - 2.0f * (lo + hi);
            v = fmaxf(v, 0.0f);
            float s;
            asm("sqrt.approx.f32 %0, %1;" : "=f"(s) : "f"(v));
            out[(ty * 8 + i) * NC + n] = -s;
        }
    }
}

// ---------------------------------------------------------------------------
extern "C" void kernel_launch(void* const* d_in, const int* in_sizes, int n_in,
                              void* d_out, int out_size) {
    const float* ent   = (const float*)d_in[0];   // [100000, 256] f32
    const float* rel   = (const float*)d_in[1];   // [500, 256] f32
    const int*   heads = (const int*)d_in[2];     // [128] i32
    const int*   rels  = (const int*)d_in[3];     // [128] i32
    const int*   tails = (const int*)d_in[4];     // [10000] i32
    float* out = (float*)d_out;                   // [128, 10000] f32

    const int smem_bytes = (KP * B * 2 + KP * NT * 2) * (int)sizeof(float); // 212992
    cudaFuncSetAttribute(score_kernel,
                         cudaFuncAttributeMaxDynamicSharedMemorySize, smem_bytes);

    build_left_kernel<<<B, 256>>>(ent, rel, heads, rels);
    pack_t_kernel<<<(NC + TROWS - 1) / TROWS, 256>>>(ent, tails);
    score_kernel<<<NBLK, 256, smem_bytes>>>(out);
}

// round 3
// speedup vs baseline: 2.9546x; 2.9546x over previous
#include <cuda_runtime.h>
#include <cuda_bf16.h>
#include <cstdint>

#define EMB_D    256
#define BATCH    128
#define NC       10000
#define NTILE    128
#define NBLK     ((NC + NTILE - 1) / NTILE)   // 79
#define NTHREADS 256

#define TSTRIDE  264                           // bf16 elements per row (256 + 8 pad)
#define TSTRIDE_W (TSTRIDE / 2)                // 132 words per row

// dynamic smem layout (bytes)
#define OFF_TN   0                             // float[128]
#define OFF_LN   512                           // float[128]
#define OFF_TS   1024                          // t tile   128 x 264 bf16 = 67584 B
#define OFF_LS   (1024 + 67584)                // left tile 128 x 264 bf16
#define SMEM_DYN (1024 + 2 * 67584)            // 136192 B

// ---------------------------------------------------------------------------
__device__ __forceinline__ void mma_bf16(float* c,
                                         uint32_t a0, uint32_t a1, uint32_t a2, uint32_t a3,
                                         uint32_t b0, uint32_t b1) {
    asm volatile(
        "mma.sync.aligned.m16n8k16.row.col.f32.bf16.bf16.f32 "
        "{%0,%1,%2,%3}, {%4,%5,%6,%7}, {%8,%9}, {%0,%1,%2,%3};"
        : "+f"(c[0]), "+f"(c[1]), "+f"(c[2]), "+f"(c[3])
        : "r"(a0), "r"(a1), "r"(a2), "r"(a3), "r"(b0), "r"(b1));
}

__device__ __forceinline__ uint32_t pack_bf16x2(float lo, float hi) {
    __nv_bfloat162 p = __floats2bfloat162_rn(lo, hi);
    return *reinterpret_cast<uint32_t*>(&p);
}

// reduce 8 floats (one row slice per lane) across full warp -> lane0 has total
__device__ __forceinline__ float warp_sum(float s) {
    #pragma unroll
    for (int o = 16; o; o >>= 1) s += __shfl_xor_sync(0xffffffffu, s, o);
    return s;
}

// ---------------------------------------------------------------------------
__global__ void __launch_bounds__(NTHREADS, 1)
transe_hmma_kernel(const float* __restrict__ ent, const float* __restrict__ rel,
                   const int* __restrict__ heads, const int* __restrict__ rels,
                   const int* __restrict__ tails, float* __restrict__ out) {
    extern __shared__ __align__(16) char smem[];
    float*    tn_s = reinterpret_cast<float*>(smem + OFF_TN);
    float*    ln_s = reinterpret_cast<float*>(smem + OFF_LN);
    uint32_t* tS   = reinterpret_cast<uint32_t*>(smem + OFF_TS);   // word-addressed
    uint32_t* lS   = reinterpret_cast<uint32_t*>(smem + OFF_LS);

    const int tid  = threadIdx.x;
    const int wid  = tid >> 5;
    const int lane = tid & 31;
    const int n0   = blockIdx.x * NTILE;

    // ================= gather t = ent[tails[...]]  (16 rows per warp) =======
    {
        const int rbase = wid * 16;
        #pragma unroll
        for (int j = 0; j < 16; j += 4) {
            int idx[4];
            #pragma unroll
            for (int u = 0; u < 4; u++) {
                int nn = n0 + rbase + j + u;
                idx[u] = tails[nn < NC ? nn : NC - 1];
            }
            float4 va[4], vb[4];
            #pragma unroll
            for (int u = 0; u < 4; u++) {
                const float4* src = reinterpret_cast<const float4*>(ent + (size_t)idx[u] * EMB_D);
                va[u] = src[lane * 2];
                vb[u] = src[lane * 2 + 1];
            }
            #pragma unroll
            for (int u = 0; u < 4; u++) {
                const int r = rbase + j + u;
                float s = va[u].x*va[u].x + va[u].y*va[u].y + va[u].z*va[u].z + va[u].w*va[u].w
                        + vb[u].x*vb[u].x + vb[u].y*vb[u].y + vb[u].z*vb[u].z + vb[u].w*vb[u].w;
                s = warp_sum(s);
                if (lane == 0) tn_s[r] = s;
                uint4 pk;
                pk.x = pack_bf16x2(va[u].x, va[u].y);
                pk.y = pack_bf16x2(va[u].z, va[u].w);
                pk.z = pack_bf16x2(vb[u].x, vb[u].y);
                pk.w = pack_bf16x2(vb[u].z, vb[u].w);
                *reinterpret_cast<uint4*>(tS + r * TSTRIDE_W + lane * 4) = pk;
            }
        }
    }

    // ================= build left = ent[heads]+rel[rels]  ====================
    {
        const int rbase = wid * 16;
        #pragma unroll
        for (int j = 0; j < 16; j += 4) {
            int ih[4], ir[4];
            #pragma unroll
            for (int u = 0; u < 4; u++) {
                ih[u] = heads[rbase + j + u];
                ir[u] = rels[rbase + j + u];
            }
            float4 ea[4], eb[4], ra[4], rb[4];
            #pragma unroll
            for (int u = 0; u < 4; u++) {
                const float4* eh = reinterpret_cast<const float4*>(ent + (size_t)ih[u] * EMB_D);
                const float4* rr = reinterpret_cast<const float4*>(rel + (size_t)ir[u] * EMB_D);
                ea[u] = eh[lane * 2];  eb[u] = eh[lane * 2 + 1];
                ra[u] = rr[lane * 2];  rb[u] = rr[lane * 2 + 1];
            }
            #pragma unroll
            for (int u = 0; u < 4; u++) {
                const int r = rbase + j + u;
                float v0 = ea[u].x + ra[u].x, v1 = ea[u].y + ra[u].y;
                float v2 = ea[u].z + ra[u].z, v3 = ea[u].w + ra[u].w;
                float v4 = eb[u].x + rb[u].x, v5 = eb[u].y + rb[u].y;
                float v6 = eb[u].z + rb[u].z, v7 = eb[u].w + rb[u].w;
                float s = v0*v0 + v1*v1 + v2*v2 + v3*v3 + v4*v4 + v5*v5 + v6*v6 + v7*v7;
                s = warp_sum(s);
                if (lane == 0) ln_s[r] = s;
                uint4 pk;
                pk.x = pack_bf16x2(v0, v1);
                pk.y = pack_bf16x2(v2, v3);
                pk.z = pack_bf16x2(v4, v5);
                pk.w = pack_bf16x2(v6, v7);
                *reinterpret_cast<uint4*>(lS + r * TSTRIDE_W + lane * 4) = pk;
            }
        }
    }

    __syncthreads();

    // ================= HMMA mainloop: warp tile 32 tails x 64 batch ==========
    const int m0 = (wid & 3) * 32;      // tail-row base for this warp
    const int b0 = (wid >> 2) * 64;     // batch base
    const int g   = lane >> 2;
    const int tig = lane & 3;

    float acc[2][8][4];
    #pragma unroll
    for (int mi = 0; mi < 2; mi++)
        #pragma unroll
        for (int nb = 0; nb < 8; nb++)
            #pragma unroll
            for (int c = 0; c < 4; c++) acc[mi][nb][c] = 0.0f;

    #pragma unroll 4
    for (int ks = 0; ks < 16; ks++) {
        const int kw = ks * 8 + tig;    // word offset along k for this thread

        uint32_t a[2][4];
        #pragma unroll
        for (int mi = 0; mi < 2; mi++) {
            const int rA = m0 + mi * 16 + g;
            a[mi][0] = tS[rA * TSTRIDE_W + kw];
            a[mi][1] = tS[(rA + 8) * TSTRIDE_W + kw];
            a[mi][2] = tS[rA * TSTRIDE_W + kw + 4];
            a[mi][3] = tS[(rA + 8) * TSTRIDE_W + kw + 4];
        }
        uint32_t bb[8][2];
        #pragma unroll
        for (int nb = 0; nb < 8; nb++) {
            const int rB = b0 + nb * 8 + g;
            bb[nb][0] = lS[rB * TSTRIDE_W + kw];
            bb[nb][1] = lS[rB * TSTRIDE_W + kw + 4];
        }
        #pragma unroll
        for (int mi = 0; mi < 2; mi++)
            #pragma unroll
            for (int nb = 0; nb < 8; nb++)
                mma_bf16(acc[mi][nb], a[mi][0], a[mi][1], a[mi][2], a[mi][3],
                         bb[nb][0], bb[nb][1]);
    }

    // ================= epilogue: -sqrt(ln + tn - 2*dot), direct STG ==========
    #pragma unroll
    for (int mi = 0; mi < 2; mi++) {
        const int row0 = m0 + mi * 16 + g;       // tail rows row0, row0+8
        const int nt0  = n0 + row0;
        const int nt1  = nt0 + 8;
        const float tn0 = tn_s[row0];
        const float tn1 = tn_s[row0 + 8];
        #pragma unroll
        for (int nb = 0; nb < 8; nb++) {
            const int bc = b0 + nb * 8 + tig * 2;  // batch cols bc, bc+1
            const float l0 = ln_s[bc], l1 = ln_s[bc + 1];
            float* acc4 = acc[mi][nb];
            float v, sq;
            if (nt0 < NC) {
                v = fmaxf(l0 + tn0 - 2.0f * acc4[0], 0.0f);
                asm("sqrt.approx.f32 %0, %1;" : "=f"(sq) : "f"(v));
                out[(size_t)bc * NC + nt0] = -sq;
                v = fmaxf(l1 + tn0 - 2.0f * acc4[1], 0.0f);
                asm("sqrt.approx.f32 %0, %1;" : "=f"(sq) : "f"(v));
                out[(size_t)(bc + 1) * NC + nt0] = -sq;
            }
            if (nt1 < NC) {
                v = fmaxf(l0 + tn1 - 2.0f * acc4[2], 0.0f);
                asm("sqrt.approx.f32 %0, %1;" : "=f"(sq) : "f"(v));
                out[(size_t)bc * NC + nt1] = -sq;
                v = fmaxf(l1 + tn1 - 2.0f * acc4[3], 0.0f);
                asm("sqrt.approx.f32 %0, %1;" : "=f"(sq) : "f"(v));
                out[(size_t)(bc + 1) * NC + nt1] = -sq;
            }
        }
    }
}

// ---------------------------------------------------------------------------
extern "C" void kernel_launch(void* const* d_in, const int* in_sizes, int n_in,
                              void* d_out, int out_size) {
    const float* ent   = (const float*)d_in[0];
    const float* rel   = (const float*)d_in[1];
    const int*   heads = (const int*)d_in[2];
    const int*   rels  = (const int*)d_in[3];
    const int*   tails = (const int*)d_in[4];
    float* out = (float*)d_out;

    cudaFuncSetAttribute(transe_hmma_kernel,
                         cudaFuncAttributeMaxDynamicSharedMemorySize, SMEM_DYN);
    transe_hmma_kernel<<<NBLK, NTHREADS, SMEM_DYN>>>(ent, rel, heads, rels, tails, out);
}

// round 4
// speedup vs baseline: 3.3612x; 1.1376x over previous
#include <cuda_runtime.h>
#include <cuda_bf16.h>
#include <cstdint>

#define EMB_D    256
#define BATCH    128
#define NC       10000
#define NTILE    80                            // tails per CTA; 125 * 80 = 10000 exact
#define NBLK     (NC / NTILE)                  // 125 CTAs = one wave on 148 SMs
#define NTHREADS 512                           // 16 warps

#define TSTRIDE_W 132                          // words per row (256 bf16 = 128 words + 4 pad)

// dynamic smem layout (bytes)
#define OFF_LN   0                             // float[128]  (left norms)
#define OFF_TN   512                           // float[80]   (tail norms)
#define OFF_LS   1024                          // left tile 128 x 264 bf16 = 67584 B
#define OFF_TS   (1024 + 67584)                // t tile     80 x 264 bf16 = 42240 B
#define SMEM_DYN (1024 + 67584 + 42240)        // 110848 B

// ---------------------------------------------------------------------------
__device__ __forceinline__ void mma_bf16(float* c,
                                         uint32_t a0, uint32_t a1, uint32_t a2, uint32_t a3,
                                         uint32_t b0, uint32_t b1) {
    asm volatile(
        "mma.sync.aligned.m16n8k16.row.col.f32.bf16.bf16.f32 "
        "{%0,%1,%2,%3}, {%4,%5,%6,%7}, {%8,%9}, {%0,%1,%2,%3};"
        : "+f"(c[0]), "+f"(c[1]), "+f"(c[2]), "+f"(c[3])
        : "r"(a0), "r"(a1), "r"(a2), "r"(a3), "r"(b0), "r"(b1));
}

__device__ __forceinline__ uint32_t pack_bf16x2(float lo, float hi) {
    __nv_bfloat162 p = __floats2bfloat162_rn(lo, hi);
    return *reinterpret_cast<uint32_t*>(&p);
}

__device__ __forceinline__ float warp_sum(float s) {
    #pragma unroll
    for (int o = 16; o; o >>= 1) s += __shfl_xor_sync(0xffffffffu, s, o);
    return s;
}

// ---------------------------------------------------------------------------
__global__ void __launch_bounds__(NTHREADS, 1)
transe_hmma_kernel(const float* __restrict__ ent, const float* __restrict__ rel,
                   const int* __restrict__ heads, const int* __restrict__ rels,
                   const int* __restrict__ tails, float* __restrict__ out) {
    extern __shared__ __align__(16) char smem[];
    float*    ln_s = reinterpret_cast<float*>(smem + OFF_LN);
    float*    tn_s = reinterpret_cast<float*>(smem + OFF_TN);
    uint32_t* lS   = reinterpret_cast<uint32_t*>(smem + OFF_LS);
    uint32_t* tS   = reinterpret_cast<uint32_t*>(smem + OFF_TS);

    const int tid  = threadIdx.x;
    const int wid  = tid >> 5;                  // 0..15
    const int lane = tid & 31;
    const int n0   = blockIdx.x * NTILE;

    // ============ gather t = ent[tails]: 5 rows per warp (80 total) =========
    {
        const int rbase = wid * 5;
        int idx[5];
        #pragma unroll
        for (int u = 0; u < 5; u++) idx[u] = tails[n0 + rbase + u];
        float4 va[5], vb[5];
        #pragma unroll
        for (int u = 0; u < 5; u++) {
            const float4* src = reinterpret_cast<const float4*>(ent + (size_t)idx[u] * EMB_D);
            va[u] = src[lane * 2];
            vb[u] = src[lane * 2 + 1];
        }
        #pragma unroll
        for (int u = 0; u < 5; u++) {
            const int r = rbase + u;
            float s = va[u].x*va[u].x + va[u].y*va[u].y + va[u].z*va[u].z + va[u].w*va[u].w
                    + vb[u].x*vb[u].x + vb[u].y*vb[u].y + vb[u].z*vb[u].z + vb[u].w*vb[u].w;
            s = warp_sum(s);
            if (lane == 0) tn_s[r] = s;
            uint4 pk;
            pk.x = pack_bf16x2(va[u].x, va[u].y);
            pk.y = pack_bf16x2(va[u].z, va[u].w);
            pk.z = pack_bf16x2(vb[u].x, vb[u].y);
            pk.w = pack_bf16x2(vb[u].z, vb[u].w);
            *reinterpret_cast<uint4*>(tS + r * TSTRIDE_W + lane * 4) = pk;
        }
    }

    // ============ build left = ent[heads]+rel[rels]: 8 rows per warp =========
    {
        const int rbase = wid * 8;
        #pragma unroll
        for (int j = 0; j < 8; j += 4) {
            int ih[4], ir[4];
            #pragma unroll
            for (int u = 0; u < 4; u++) {
                ih[u] = heads[rbase + j + u];
                ir[u] = rels[rbase + j + u];
            }
            float4 ea[4], eb[4], ra[4], rb[4];
            #pragma unroll
            for (int u = 0; u < 4; u++) {
                const float4* eh = reinterpret_cast<const float4*>(ent + (size_t)ih[u] * EMB_D);
                const float4* rr = reinterpret_cast<const float4*>(rel + (size_t)ir[u] * EMB_D);
                ea[u] = eh[lane * 2];  eb[u] = eh[lane * 2 + 1];
                ra[u] = rr[lane * 2];  rb[u] = rr[lane * 2 + 1];
            }
            #pragma unroll
            for (int u = 0; u < 4; u++) {
                const int r = rbase + j + u;
                float v0 = ea[u].x + ra[u].x, v1 = ea[u].y + ra[u].y;
                float v2 = ea[u].z + ra[u].z, v3 = ea[u].w + ra[u].w;
                float v4 = eb[u].x + rb[u].x, v5 = eb[u].y + rb[u].y;
                float v6 = eb[u].z + rb[u].z, v7 = eb[u].w + rb[u].w;
                float s = v0*v0 + v1*v1 + v2*v2 + v3*v3 + v4*v4 + v5*v5 + v6*v6 + v7*v7;
                s = warp_sum(s);
                if (lane == 0) ln_s[r] = s;
                uint4 pk;
                pk.x = pack_bf16x2(v0, v1);
                pk.y = pack_bf16x2(v2, v3);
                pk.z = pack_bf16x2(v4, v5);
                pk.w = pack_bf16x2(v6, v7);
                *reinterpret_cast<uint4*>(lS + r * TSTRIDE_W + lane * 4) = pk;
            }
        }
    }

    __syncthreads();

    // ============ HMMA mainloop: warp tile 16(batch) x 40(tails) =============
    // warps: 8 along m (batch), 2 along n (tails)
    const int m0  = (wid & 7) * 16;             // batch row base
    const int nw0 = (wid >> 3) * 40;            // tail col base
    const int g   = lane >> 2;
    const int tig = lane & 3;

    float acc[5][4];
    #pragma unroll
    for (int nb = 0; nb < 5; nb++)
        #pragma unroll
        for (int c = 0; c < 4; c++) acc[nb][c] = 0.0f;

    const int rA0 = (m0 + g) * TSTRIDE_W;
    const int rA1 = (m0 + 8 + g) * TSTRIDE_W;

    #pragma unroll 4
    for (int ks = 0; ks < 16; ks++) {
        const int kw = ks * 8 + tig;

        uint32_t a0 = lS[rA0 + kw];
        uint32_t a1 = lS[rA1 + kw];
        uint32_t a2 = lS[rA0 + kw + 4];
        uint32_t a3 = lS[rA1 + kw + 4];

        uint32_t bb[5][2];
        #pragma unroll
        for (int nb = 0; nb < 5; nb++) {
            const int rB = (nw0 + nb * 8 + g) * TSTRIDE_W;
            bb[nb][0] = tS[rB + kw];
            bb[nb][1] = tS[rB + kw + 4];
        }
        #pragma unroll
        for (int nb = 0; nb < 5; nb++)
            mma_bf16(acc[nb], a0, a1, a2, a3, bb[nb][0], bb[nb][1]);
    }

    // ============ epilogue: -sqrt(ln + tn - 2*dot) ===========================
    const int b0r = m0 + g;                     // batch rows b0r, b0r+8
    const float l0 = ln_s[b0r];
    const float l1 = ln_s[b0r + 8];

    #pragma unroll
    for (int nb = 0; nb < 5; nb++) {
        const int col = nw0 + nb * 8 + tig * 2; // tail cols col, col+1
        const int n   = n0 + col;
        const float t0 = tn_s[col];
        const float t1 = tn_s[col + 1];
        float v, sq;
        float2 w0, w1;

        v = fmaxf(l0 + t0 - 2.0f * acc[nb][0], 0.0f);
        asm("sqrt.approx.f32 %0, %1;" : "=f"(sq) : "f"(v));  w0.x = -sq;
        v = fmaxf(l0 + t1 - 2.0f * acc[nb][1], 0.0f);
        asm("sqrt.approx.f32 %0, %1;" : "=f"(sq) : "f"(v));  w0.y = -sq;
        v = fmaxf(l1 + t0 - 2.0f * acc[nb][2], 0.0f);
        asm("sqrt.approx.f32 %0, %1;" : "=f"(sq) : "f"(v));  w1.x = -sq;
        v = fmaxf(l1 + t1 - 2.0f * acc[nb][3], 0.0f);
        asm("sqrt.approx.f32 %0, %1;" : "=f"(sq) : "f"(v));  w1.y = -sq;

        *reinterpret_cast<float2*>(out + (size_t)b0r * NC + n)       = w0;
        *reinterpret_cast<float2*>(out + (size_t)(b0r + 8) * NC + n) = w1;
    }
}

// ---------------------------------------------------------------------------
extern "C" void kernel_launch(void* const* d_in, const int* in_sizes, int n_in,
                              void* d_out, int out_size) {
    const float* ent   = (const float*)d_in[0];
    const float* rel   = (const float*)d_in[1];
    const int*   heads = (const int*)d_in[2];
    const int*   rels  = (const int*)d_in[3];
    const int*   tails = (const int*)d_in[4];
    float* out = (float*)d_out;

    cudaFuncSetAttribute(transe_hmma_kernel,
                         cudaFuncAttributeMaxDynamicSharedMemorySize, SMEM_DYN);
    transe_hmma_kernel<<<NBLK, NTHREADS, SMEM_DYN>>>(ent, rel, heads, rels, tails, out);
}

// round 5
// speedup vs baseline: 3.4200x; 1.0175x over previous
#include <cuda_runtime.h>
#include <cuda_bf16.h>
#include <cstdint>

#define EMB_D    256
#define BATCH    128
#define NC       10000
#define NTILE    40                            // tails per CTA; 250 * 40 = 10000 exact
#define NBLK     (NC / NTILE)                  // 250 CTAs -> 2 per SM
#define NTHREADS 256                           // 8 warps

#define TSTRIDE_W 132                          // smem words per row (128 + 4 pad)

// dynamic smem layout (bytes)
#define OFF_LN   0                             // float[128]
#define OFF_TN   512                           // float[40] (padded)
#define OFF_LS   1024                          // left tile 128 x 264 bf16 = 67584 B
#define OFF_TS   (1024 + 67584)                // t tile     40 x 264 bf16 = 21120 B
#define SMEM_DYN (1024 + 67584 + 21120)        // 89728 B

// device-global scratch (left, bf16-packed, unpadded 32 uint4 per row)
__device__ __align__(16) uint4 g_leftT[BATCH * 32];
__device__ float g_ln[BATCH];

// ---------------------------------------------------------------------------
__device__ __forceinline__ void mma_bf16(float* c,
                                         uint32_t a0, uint32_t a1, uint32_t a2, uint32_t a3,
                                         uint32_t b0, uint32_t b1) {
    asm volatile(
        "mma.sync.aligned.m16n8k16.row.col.f32.bf16.bf16.f32 "
        "{%0,%1,%2,%3}, {%4,%5,%6,%7}, {%8,%9}, {%0,%1,%2,%3};"
        : "+f"(c[0]), "+f"(c[1]), "+f"(c[2]), "+f"(c[3])
        : "r"(a0), "r"(a1), "r"(a2), "r"(a3), "r"(b0), "r"(b1));
}

__device__ __forceinline__ uint32_t pack_bf16x2(float lo, float hi) {
    __nv_bfloat162 p = __floats2bfloat162_rn(lo, hi);
    return *reinterpret_cast<uint32_t*>(&p);
}

__device__ __forceinline__ float warp_sum(float s) {
    #pragma unroll
    for (int o = 16; o; o >>= 1) s += __shfl_xor_sync(0xffffffffu, s, o);
    return s;
}

// ---------------------------------------------------------------------------
// Kernel 1: left = ent[heads] + rel[rels] -> bf16 packed rows + fp32 norms.
// 16 blocks x 256 threads; each warp builds one row (8 rows per block).
// ---------------------------------------------------------------------------
__global__ void __launch_bounds__(NTHREADS)
build_left_kernel(const float* __restrict__ ent, const float* __restrict__ rel,
                  const int* __restrict__ heads, const int* __restrict__ rels) {
    const int wid  = threadIdx.x >> 5;
    const int lane = threadIdx.x & 31;
    const int r    = blockIdx.x * 8 + wid;

    const int h  = heads[r];
    const int rl = rels[r];
    const float4* eh = reinterpret_cast<const float4*>(ent + (size_t)h * EMB_D);
    const float4* rr = reinterpret_cast<const float4*>(rel + (size_t)rl * EMB_D);
    float4 a0 = eh[lane * 2], a1 = eh[lane * 2 + 1];
    float4 b0 = rr[lane * 2], b1 = rr[lane * 2 + 1];
    float v0 = a0.x + b0.x, v1 = a0.y + b0.y, v2 = a0.z + b0.z, v3 = a0.w + b0.w;
    float v4 = a1.x + b1.x, v5 = a1.y + b1.y, v6 = a1.z + b1.z, v7 = a1.w + b1.w;

    float s = v0*v0 + v1*v1 + v2*v2 + v3*v3 + v4*v4 + v5*v5 + v6*v6 + v7*v7;
    s = warp_sum(s);
    if (lane == 0) g_ln[r] = s;

    uint4 pk;
    pk.x = pack_bf16x2(v0, v1);
    pk.y = pack_bf16x2(v2, v3);
    pk.z = pack_bf16x2(v4, v5);
    pk.w = pack_bf16x2(v6, v7);
    g_leftT[r * 32 + lane] = pk;
}

// ---------------------------------------------------------------------------
// Kernel 2: score. Tile = 128 batch x 40 tails. 8 warps, warp tile 16x40.
// 2 CTAs per SM for gather/MMA overlap.
// ---------------------------------------------------------------------------
__global__ void __launch_bounds__(NTHREADS, 2)
score_kernel(const float* __restrict__ ent, const int* __restrict__ tails,
             float* __restrict__ out) {
    extern __shared__ __align__(16) char smem[];
    float*    ln_s = reinterpret_cast<float*>(smem + OFF_LN);
    float*    tn_s = reinterpret_cast<float*>(smem + OFF_TN);
    uint32_t* lS   = reinterpret_cast<uint32_t*>(smem + OFF_LS);
    uint32_t* tS   = reinterpret_cast<uint32_t*>(smem + OFF_TS);

    const int tid  = threadIdx.x;
    const int wid  = tid >> 5;                  // 0..7
    const int lane = tid & 31;
    const int n0   = blockIdx.x * NTILE;

    // ---- gather t = ent[tails]: 5 rows per warp ----
    {
        const int rbase = wid * 5;
        int idx[5];
        #pragma unroll
        for (int u = 0; u < 5; u++) idx[u] = tails[n0 + rbase + u];
        float4 va[5], vb[5];
        #pragma unroll
        for (int u = 0; u < 5; u++) {
            const float4* src = reinterpret_cast<const float4*>(ent + (size_t)idx[u] * EMB_D);
            va[u] = src[lane * 2];
            vb[u] = src[lane * 2 + 1];
        }
        #pragma unroll
        for (int u = 0; u < 5; u++) {
            const int r = rbase + u;
            float s = va[u].x*va[u].x + va[u].y*va[u].y + va[u].z*va[u].z + va[u].w*va[u].w
                    + vb[u].x*vb[u].x + vb[u].y*vb[u].y + vb[u].z*vb[u].z + vb[u].w*vb[u].w;
            s = warp_sum(s);
            if (lane == 0) tn_s[r] = s;
            uint4 pk;
            pk.x = pack_bf16x2(va[u].x, va[u].y);
            pk.y = pack_bf16x2(va[u].z, va[u].w);
            pk.z = pack_bf16x2(vb[u].x, vb[u].y);
            pk.w = pack_bf16x2(vb[u].z, vb[u].w);
            *reinterpret_cast<uint4*>(tS + r * TSTRIDE_W + lane * 4) = pk;
        }
    }

    // ---- stream precomputed left into padded smem rows (contiguous LDG) ----
    {
        #pragma unroll
        for (int it = 0; it < 16; it++) {
            const int u   = it * NTHREADS + tid;     // uint4 index, 4096 total
            const int row = u >> 5;                  // 32 uint4 per row
            const int c   = u & 31;
            uint4 pk = g_leftT[u];
            *reinterpret_cast<uint4*>(lS + row * TSTRIDE_W + c * 4) = pk;
        }
        if (tid < BATCH) ln_s[tid] = g_ln[tid];
    }

    __syncthreads();

    // ---- HMMA mainloop: warp tile 16(batch) x 40(tails) ----
    const int m0  = wid * 16;
    const int g   = lane >> 2;
    const int tig = lane & 3;

    float acc[5][4];
    #pragma unroll
    for (int nb = 0; nb < 5; nb++)
        #pragma unroll
        for (int c = 0; c < 4; c++) acc[nb][c] = 0.0f;

    const int rA0 = (m0 + g) * TSTRIDE_W;
    const int rA1 = (m0 + 8 + g) * TSTRIDE_W;

    #pragma unroll 4
    for (int ks = 0; ks < 16; ks++) {
        const int kw = ks * 8 + tig;

        uint32_t a0 = lS[rA0 + kw];
        uint32_t a1 = lS[rA1 + kw];
        uint32_t a2 = lS[rA0 + kw + 4];
        uint32_t a3 = lS[rA1 + kw + 4];

        uint32_t bb[5][2];
        #pragma unroll
        for (int nb = 0; nb < 5; nb++) {
            const int rB = (nb * 8 + g) * TSTRIDE_W;
            bb[nb][0] = tS[rB + kw];
            bb[nb][1] = tS[rB + kw + 4];
        }
        #pragma unroll
        for (int nb = 0; nb < 5; nb++)
            mma_bf16(acc[nb], a0, a1, a2, a3, bb[nb][0], bb[nb][1]);
    }

    // ---- epilogue: -sqrt(ln + tn - 2*dot) ----
    const int b0r = m0 + g;
    const float l0 = ln_s[b0r];
    const float l1 = ln_s[b0r + 8];

    #pragma unroll
    for (int nb = 0; nb < 5; nb++) {
        const int col = nb * 8 + tig * 2;
        const int n   = n0 + col;
        const float t0 = tn_s[col];
        const float t1 = tn_s[col + 1];
        float v, sq;
        float2 w0, w1;

        v = fmaxf(l0 + t0 - 2.0f * acc[nb][0], 0.0f);
        asm("sqrt.approx.f32 %0, %1;" : "=f"(sq) : "f"(v));  w0.x = -sq;
        v = fmaxf(l0 + t1 - 2.0f * acc[nb][1], 0.0f);
        asm("sqrt.approx.f32 %0, %1;" : "=f"(sq) : "f"(v));  w0.y = -sq;
        v = fmaxf(l1 + t0 - 2.0f * acc[nb][2], 0.0f);
        asm("sqrt.approx.f32 %0, %1;" : "=f"(sq) : "f"(v));  w1.x = -sq;
        v = fmaxf(l1 + t1 - 2.0f * acc[nb][3], 0.0f);
        asm("sqrt.approx.f32 %0, %1;" : "=f"(sq) : "f"(v));  w1.y = -sq;

        *reinterpret_cast<float2*>(out + (size_t)b0r * NC + n)       = w0;
        *reinterpret_cast<float2*>(out + (size_t)(b0r + 8) * NC + n) = w1;
    }
}

// ---------------------------------------------------------------------------
extern "C" void kernel_launch(void* const* d_in, const int* in_sizes, int n_in,
                              void* d_out, int out_size) {
    const float* ent   = (const float*)d_in[0];
    const float* rel   = (const float*)d_in[1];
    const int*   heads = (const int*)d_in[2];
    const int*   rels  = (const int*)d_in[3];
    const int*   tails = (const int*)d_in[4];
    float* out = (float*)d_out;

    cudaFuncSetAttribute(score_kernel,
                         cudaFuncAttributeMaxDynamicSharedMemorySize, SMEM_DYN);

    build_left_kernel<<<BATCH / 8, NTHREADS>>>(ent, rel, heads, rels);
    score_kernel<<<NBLK, NTHREADS, SMEM_DYN>>>(ent, tails, out);
}